// round 1
// baseline (speedup 1.0000x reference)
#include <cuda_runtime.h>

// Fixed problem shape (validated against in_sizes at runtime)
#define NMAX 100000
#define EMAX 1000000

// ---- scratch (device globals; no allocation allowed) ----
__device__ int   g_cnt[NMAX];          // per-node degree count (incl self loop)
__device__ int   g_rowoff[NMAX + 1];   // CSR row offsets
__device__ int   g_cursor[NMAX];       // fill cursors
__device__ int   g_col[EMAX + NMAX];   // CSR column (src) indices, incl self loops
__device__ float g_dinv[NMAX];         // deg^-1/2
__device__ int   g_bsum[512];          // scan block sums
__device__ float g_t[NMAX * 64];       // GEMM output (pre-aggregation)
__device__ float g_h[NMAX * 64];       // activation (post-aggregation)

// ---------------- degree / CSR construction ----------------

__global__ void k_init(int n) {
    int i = blockIdx.x * blockDim.x + threadIdx.x;
    if (i < n) g_cnt[i] = 1;   // self loop
}

__global__ void k_count(const int* __restrict__ ei, int e) {
    int i = blockIdx.x * blockDim.x + threadIdx.x;
    if (i < e) {
        int dst = ei[e + i];   // edge_index[1][i]
        atomicAdd(&g_cnt[dst], 1);
    }
}

// per-256-block exclusive scan of counts; block totals to g_bsum
__global__ void k_scan_block(int n) {
    __shared__ int s[256];
    int t = threadIdx.x;
    int i = blockIdx.x * 256 + t;
    int v = (i < n) ? g_cnt[i] : 0;
    s[t] = v;
    __syncthreads();
    for (int off = 1; off < 256; off <<= 1) {
        int a = (t >= off) ? s[t - off] : 0;
        __syncthreads();
        s[t] += a;
        __syncthreads();
    }
    if (i < n) g_rowoff[i] = s[t] - v;          // exclusive within block
    if (t == 255) g_bsum[blockIdx.x] = s[255];  // block total
}

// single-block exclusive scan of the (<=512) block sums
__global__ void k_scan_bsum(int nb) {
    __shared__ int s[512];
    int t = threadIdx.x;
    int v = (t < nb) ? g_bsum[t] : 0;
    s[t] = v;
    __syncthreads();
    for (int off = 1; off < 512; off <<= 1) {
        int a = (t >= off) ? s[t - off] : 0;
        __syncthreads();
        s[t] += a;
        __syncthreads();
    }
    g_bsum[t] = s[t] - v;  // exclusive
}

__global__ void k_finalize(int n, int e) {
    int i = blockIdx.x * blockDim.x + threadIdx.x;
    if (i < n) {
        int v = g_rowoff[i] + g_bsum[i >> 8];
        g_rowoff[i] = v;
        g_cursor[i] = v;
        g_dinv[i]   = rsqrtf((float)g_cnt[i]);
    }
    if (i == 0) g_rowoff[n] = e + n;
}

__global__ void k_fill(const int* __restrict__ ei, int e, int n) {
    int i = blockIdx.x * blockDim.x + threadIdx.x;
    int src, dst;
    if (i < e) {
        src = ei[i];        // edge_index[0][i]
        dst = ei[e + i];    // edge_index[1][i]
    } else if (i < e + n) {
        src = dst = i - e;  // self loop
    } else {
        return;
    }
    int pos = atomicAdd(&g_cursor[dst], 1);
    g_col[pos] = src;
}

// ---------------- dense GEMM: Y[n,F] = X[n,64] @ W[64,F] (+bias) ----------------
// 64 rows per block, 256 threads. Xs padded to 65 to avoid bank conflicts on Xs[r][k].

template <int F>
__global__ void __launch_bounds__(256) k_gemm(const float* __restrict__ X,
                                              const float* __restrict__ W,
                                              const float* __restrict__ bias,
                                              float* __restrict__ Y, int n) {
    __shared__ float Xs[64][65];
    __shared__ float Ws[64 * F];
    int t  = threadIdx.x;
    int r0 = blockIdx.x * 64;

    for (int i = t; i < 64 * F; i += 256) Ws[i] = W[i];
    for (int i = t; i < 64 * 64; i += 256) {
        int r = i >> 6, c = i & 63;
        Xs[r][c] = (r0 + r < n) ? X[(size_t)(r0 + r) * 64 + c] : 0.f;
    }
    __syncthreads();

    if (F == 64) {
        int r = t >> 2, c0 = (t & 3) * 16;
        float acc[16];
#pragma unroll
        for (int j = 0; j < 16; j++) acc[j] = 0.f;
#pragma unroll
        for (int k = 0; k < 64; k++) {
            float xv = Xs[r][k];
#pragma unroll
            for (int j = 0; j < 16; j++)
                acc[j] = fmaf(xv, Ws[k * 64 + c0 + j], acc[j]);
        }
        if (r0 + r < n) {
#pragma unroll
            for (int j = 0; j < 16; j++)
                Y[(size_t)(r0 + r) * 64 + c0 + j] = acc[j];
        }
    } else {  // F == 32, with bias (final classifier)
        int r = t >> 2, c0 = (t & 3) * 8;
        float acc[8];
#pragma unroll
        for (int j = 0; j < 8; j++) acc[j] = 0.f;
#pragma unroll
        for (int k = 0; k < 64; k++) {
            float xv = Xs[r][k];
#pragma unroll
            for (int j = 0; j < 8; j++)
                acc[j] = fmaf(xv, Ws[k * F + c0 + j], acc[j]);
        }
        if (r0 + r < n) {
#pragma unroll
            for (int j = 0; j < 8; j++)
                Y[(size_t)(r0 + r) * F + c0 + j] = acc[j] + bias[c0 + j];
        }
    }
}

// ---------------- sparse aggregation: h[dst] = relu(dinv[dst]*sum(dinv[src]*t[src]) + b) ----------------
// one warp per destination row; lane handles a float2 of the 64 features

__global__ void __launch_bounds__(256) k_agg(const float* __restrict__ t,
                                             float* __restrict__ h,
                                             const float* __restrict__ bias,
                                             int n) {
    int warp = (blockIdx.x * blockDim.x + threadIdx.x) >> 5;
    int lane = threadIdx.x & 31;
    if (warp >= n) return;
    int start = g_rowoff[warp];
    int end   = g_rowoff[warp + 1];
    int f = lane * 2;
    float ax = 0.f, ay = 0.f;
    for (int j = start; j < end; j++) {
        int s = g_col[j];
        float w = g_dinv[s];
        float2 v = *(const float2*)&t[(size_t)s * 64 + f];
        ax = fmaf(w, v.x, ax);
        ay = fmaf(w, v.y, ay);
    }
    float d  = g_dinv[warp];
    float ox = fmaf(d, ax, bias[f]);
    float oy = fmaf(d, ay, bias[f + 1]);
    ox = fmaxf(ox, 0.f);
    oy = fmaxf(oy, 0.f);
    *(float2*)&h[(size_t)warp * 64 + f] = make_float2(ox, oy);
}

// ---------------- launch ----------------

extern "C" void kernel_launch(void* const* d_in, const int* in_sizes, int n_in,
                              void* d_out, int out_size) {
    const float* x  = (const float*)d_in[0];
    const int*   ei = (const int*)d_in[1];
    const float* W1 = (const float*)d_in[2];
    const float* b1 = (const float*)d_in[3];
    const float* W2 = (const float*)d_in[4];
    const float* b2 = (const float*)d_in[5];
    const float* Wl = (const float*)d_in[6];
    const float* bl = (const float*)d_in[7];
    float* out = (float*)d_out;

    int n = in_sizes[0] / 64;   // 100000
    int e = in_sizes[1] / 2;    // 1000000

    float* t_ptr = nullptr;
    float* h_ptr = nullptr;
    cudaGetSymbolAddress((void**)&t_ptr, g_t);
    cudaGetSymbolAddress((void**)&h_ptr, g_h);

    int nb = (n + 255) / 256;

    // CSR + normalization build
    k_init<<<nb, 256>>>(n);
    k_count<<<(e + 255) / 256, 256>>>(ei, e);
    k_scan_block<<<nb, 256>>>(n);
    k_scan_bsum<<<1, 512>>>(nb);
    k_finalize<<<nb, 256>>>(n, e);
    k_fill<<<(e + n + 255) / 256, 256>>>(ei, e, n);

    int gemm_blocks = (n + 63) / 64;
    int agg_blocks  = (n + 7) / 8;  // 8 warps per 256-thread block

    // layer 1: t = x@W1 ; h = relu(agg(t)+b1)
    k_gemm<64><<<gemm_blocks, 256>>>(x, W1, nullptr, t_ptr, n);
    k_agg<<<agg_blocks, 256>>>(t_ptr, h_ptr, b1, n);
    // layer 2
    k_gemm<64><<<gemm_blocks, 256>>>(h_ptr, W2, nullptr, t_ptr, n);
    k_agg<<<agg_blocks, 256>>>(t_ptr, h_ptr, b2, n);
    // classifier
    k_gemm<32><<<gemm_blocks, 256>>>(h_ptr, Wl, bl, out, n);
}

// round 2
// speedup vs baseline: 3.1980x; 3.1980x over previous
#include <cuda_runtime.h>

#define NMAX 100000
#define EMAX 1000000

// ---- scratch (device globals; no allocation allowed) ----
__device__ int   g_cnt[NMAX];          // per-node in-degree (excl self loop)
__device__ int   g_rowoff[NMAX + 1];   // CSR row offsets
__device__ int   g_cursor[NMAX];       // fill cursors
__device__ int   g_col[EMAX + NMAX];   // CSR column (src) indices incl self loops
__device__ float g_dinv[NMAX];         // (deg incl self loop)^-1/2
__device__ int   g_bsum[512];          // scan block sums
__device__ float g_t[NMAX * 64];       // GEMM output, pre-scaled by dinv[row]
__device__ float g_h[NMAX * 64];       // activation

// ---------------- CSR construction ----------------

__global__ void k_count(const int* __restrict__ ei, int e) {
    int i = blockIdx.x * blockDim.x + threadIdx.x;
    if (i < e) atomicAdd(&g_cnt[ei[e + i]], 1);
}

// per-256-block exclusive scan of (cnt+1); block totals to g_bsum
__global__ void __launch_bounds__(256) k_scan_block(int n) {
    __shared__ int wsum[8];
    int t = threadIdx.x;
    int i = blockIdx.x * 256 + t;
    int v = (i < n) ? g_cnt[i] + 1 : 0;   // +1 = self loop
    int lane = t & 31, w = t >> 5;
    int s = v;
#pragma unroll
    for (int o = 1; o < 32; o <<= 1) {
        int a = __shfl_up_sync(0xffffffffu, s, o);
        if (lane >= o) s += a;
    }
    if (lane == 31) wsum[w] = s;
    __syncthreads();
    if (w == 0) {
        int ws = (lane < 8) ? wsum[lane] : 0;
#pragma unroll
        for (int o = 1; o < 8; o <<= 1) {
            int a = __shfl_up_sync(0xffffffffu, ws, o);
            if (lane >= o) ws += a;
        }
        if (lane < 8) wsum[lane] = ws;   // inclusive warp sums
    }
    __syncthreads();
    int excl = s - v + (w > 0 ? wsum[w - 1] : 0);
    if (i < n) g_rowoff[i] = excl;
    if (t == 255) g_bsum[blockIdx.x] = excl + v;
}

// single-block exclusive scan of (<=512) block sums
__global__ void __launch_bounds__(512) k_scan_bsum(int nb) {
    __shared__ int wsum[16];
    int t = threadIdx.x, lane = t & 31, w = t >> 5;
    int v = (t < nb) ? g_bsum[t] : 0;
    int s = v;
#pragma unroll
    for (int o = 1; o < 32; o <<= 1) {
        int a = __shfl_up_sync(0xffffffffu, s, o);
        if (lane >= o) s += a;
    }
    if (lane == 31) wsum[w] = s;
    __syncthreads();
    if (w == 0) {
        int ws = (lane < 16) ? wsum[lane] : 0;
#pragma unroll
        for (int o = 1; o < 16; o <<= 1) {
            int a = __shfl_up_sync(0xffffffffu, ws, o);
            if (lane >= o) ws += a;
        }
        if (lane < 16) wsum[lane] = ws;
    }
    __syncthreads();
    g_bsum[t] = s - v + (w > 0 ? wsum[w - 1] : 0);
}

__global__ void k_finalize(int n, int e) {
    int i = blockIdx.x * blockDim.x + threadIdx.x;
    if (i < n) {
        int v = g_rowoff[i] + g_bsum[i >> 8];
        g_rowoff[i] = v;
        g_cursor[i] = v;
        g_dinv[i]   = rsqrtf((float)(g_cnt[i] + 1));
    }
    if (i == 0) g_rowoff[n] = e + n;
}

__global__ void k_fill(const int* __restrict__ ei, int e, int n) {
    int i = blockIdx.x * blockDim.x + threadIdx.x;
    int src, dst;
    if (i < e) {
        src = ei[i];
        dst = ei[e + i];
    } else if (i < e + n) {
        src = dst = i - e;
    } else {
        return;
    }
    int pos = atomicAdd(&g_cursor[dst], 1);
    g_col[pos] = src;
}

// ---------------- dense GEMM: Y[n,F] = (X[n,64] @ W[64,F]) * dinv[row]  (or +bias) ----------------
// 128 threads, 128 rows/block. Each thread: 4 rows x (F/4) cols.
// Xs swizzled (k ^ ((row>>2 & 7)<<2)) for conflict-free reads at stride 64.

template <int F, bool SCALE>
__global__ void __launch_bounds__(128) k_gemm(const float* __restrict__ X,
                                              const float* __restrict__ W,
                                              const float* __restrict__ bias,
                                              const float* __restrict__ dinv,
                                              float* __restrict__ Y, int n) {
    constexpr int C = F / 4;                 // 16 (F=64) or 8 (F=32)
    __shared__ float Xs[128 * 64];
    __shared__ float Ws[64 * F];
    int t  = threadIdx.x;
    int r0 = blockIdx.x * 128;

    for (int i = t; i < 64 * F / 4; i += 128)
        ((float4*)Ws)[i] = ((const float4*)W)[i];
    for (int i = t; i < 128 * 16; i += 128) {
        int r  = i >> 4;
        int k4 = (i & 15) << 2;
        int sw = ((r >> 2) & 7) << 2;
        float4 v = make_float4(0.f, 0.f, 0.f, 0.f);
        if (r0 + r < n) v = *(const float4*)&X[(size_t)(r0 + r) * 64 + k4];
        *(float4*)&Xs[r * 64 + (k4 ^ sw)] = v;
    }
    __syncthreads();

    int cg = t & 3, tr = t >> 2;
    int c0 = cg * C;
    int sw = (tr & 7) << 2;                  // row>>2 == tr for all 4 rows of this thread

    float acc[4][C];
#pragma unroll
    for (int rr = 0; rr < 4; rr++)
#pragma unroll
        for (int j = 0; j < C; j++) acc[rr][j] = 0.f;

#pragma unroll
    for (int k = 0; k < 64; k++) {
        float w[C];
#pragma unroll
        for (int j = 0; j < C; j += 4)
            *(float4*)&w[j] = *(const float4*)&Ws[k * F + c0 + j];
#pragma unroll
        for (int rr = 0; rr < 4; rr++) {
            float xv = Xs[(tr * 4 + rr) * 64 + (k ^ sw)];
#pragma unroll
            for (int j = 0; j < C; j++)
                acc[rr][j] = fmaf(xv, w[j], acc[rr][j]);
        }
    }

#pragma unroll
    for (int rr = 0; rr < 4; rr++) {
        int r = r0 + tr * 4 + rr;
        if (r < n) {
            float s = SCALE ? dinv[r] : 1.f;
#pragma unroll
            for (int j = 0; j < C; j += 4) {
                float4 o;
                if (SCALE) {
                    o.x = acc[rr][j + 0] * s;
                    o.y = acc[rr][j + 1] * s;
                    o.z = acc[rr][j + 2] * s;
                    o.w = acc[rr][j + 3] * s;
                } else {
                    o.x = acc[rr][j + 0] + bias[c0 + j + 0];
                    o.y = acc[rr][j + 1] + bias[c0 + j + 1];
                    o.z = acc[rr][j + 2] + bias[c0 + j + 2];
                    o.w = acc[rr][j + 3] + bias[c0 + j + 3];
                }
                *(float4*)&Y[(size_t)r * F + c0 + j] = o;
            }
        }
    }
}

// ---------------- sparse aggregation: h[dst] = relu(dinv[dst]*sum(t[src]) + b) ----------------
// t rows are pre-scaled by dinv[src]. One warp per dst; chunked coalesced
// index load + shfl broadcast; lane handles a float2 of the 64 features.

__global__ void __launch_bounds__(256) k_agg(const float* __restrict__ t,
                                             float* __restrict__ h,
                                             const float* __restrict__ bias,
                                             int n) {
    int warp = (blockIdx.x * blockDim.x + threadIdx.x) >> 5;
    int lane = threadIdx.x & 31;
    if (warp >= n) return;
    int start = g_rowoff[warp];
    int end   = g_rowoff[warp + 1];
    int f = lane * 2;
    float ax = 0.f, ay = 0.f;
    for (int base = start; base < end; base += 32) {
        int m = min(32, end - base);
        int myc = (lane < m) ? g_col[base + lane] : 0;
        for (int u = 0; u < m; u++) {
            int s = __shfl_sync(0xffffffffu, myc, u);
            float2 v = *(const float2*)&t[(size_t)s * 64 + f];
            ax += v.x;
            ay += v.y;
        }
    }
    float d  = g_dinv[warp];
    float ox = fmaxf(fmaf(d, ax, bias[f]), 0.f);
    float oy = fmaxf(fmaf(d, ay, bias[f + 1]), 0.f);
    *(float2*)&h[(size_t)warp * 64 + f] = make_float2(ox, oy);
}

// ---------------- launch ----------------

extern "C" void kernel_launch(void* const* d_in, const int* in_sizes, int n_in,
                              void* d_out, int out_size) {
    const float* x  = (const float*)d_in[0];
    const int*   ei = (const int*)d_in[1];
    const float* W1 = (const float*)d_in[2];
    const float* b1 = (const float*)d_in[3];
    const float* W2 = (const float*)d_in[4];
    const float* b2 = (const float*)d_in[5];
    const float* Wl = (const float*)d_in[6];
    const float* bl = (const float*)d_in[7];
    float* out = (float*)d_out;

    int n = in_sizes[0] / 64;   // 100000
    int e = in_sizes[1] / 2;    // 1000000

    float* t_ptr = nullptr;
    float* h_ptr = nullptr;
    float* dinv_ptr = nullptr;
    int*   cnt_ptr = nullptr;
    cudaGetSymbolAddress((void**)&t_ptr, g_t);
    cudaGetSymbolAddress((void**)&h_ptr, g_h);
    cudaGetSymbolAddress((void**)&dinv_ptr, g_dinv);
    cudaGetSymbolAddress((void**)&cnt_ptr, g_cnt);

    int nb = (n + 255) / 256;

    // CSR + normalization build (every call; graph-capturable ops only)
    cudaMemsetAsync(cnt_ptr, 0, (size_t)n * sizeof(int));
    k_count<<<(e + 255) / 256, 256>>>(ei, e);
    k_scan_block<<<nb, 256>>>(n);
    k_scan_bsum<<<1, 512>>>(nb);
    k_finalize<<<nb, 256>>>(n, e);
    k_fill<<<(e + n + 255) / 256, 256>>>(ei, e, n);

    int gemm_blocks = (n + 127) / 128;
    int agg_blocks  = (n + 7) / 8;

    // layer 1
    k_gemm<64, true><<<gemm_blocks, 128>>>(x, W1, nullptr, dinv_ptr, t_ptr, n);
    k_agg<<<agg_blocks, 256>>>(t_ptr, h_ptr, b1, n);
    // layer 2
    k_gemm<64, true><<<gemm_blocks, 128>>>(h_ptr, W2, nullptr, dinv_ptr, t_ptr, n);
    k_agg<<<agg_blocks, 256>>>(t_ptr, h_ptr, b2, n);
    // classifier
    k_gemm<32, false><<<gemm_blocks, 128>>>(h_ptr, Wl, bl, dinv_ptr, out, n);
}